// round 17
// baseline (speedup 1.0000x reference)
#include <cuda_runtime.h>
#include <cstdint>

#define BB 16
#define HH 1024
#define WW 1024
#define WORDS 32                    // uint32 words per row
#define HW (HH * WW)
#define NPIX (BB * HW)
#define NWORDS (BB * HH * WORDS)

#define GRPS 16                     // one group per image
#define GBLKN 37                    // blocks per group
#define NBLK (GRPS * GBLKN)         // 592 = 148 SMs x 4, co-resident
#define NTHR 256
#define GTHREADS (GBLKN * NTHR)     // threads per group (9472)
#define GWARPS (GTHREADS / 32)      // warps per group (296)

#define WPI (HH * WORDS)            // words per image (32768)
#define PAIRS_IMG (HH / 2)          // 512 row-pairs per image

__device__ unsigned int g_tbits[NWORDS];   // packed target bits (2 MiB)
__device__ uint2        g_te[NWORDS];      // (tbits, ebits) interleaved (4 MiB)
__device__ unsigned long long g_ecount;
__device__ double g_A;
__device__ double g_B;
__device__ unsigned g_done;
__device__ unsigned g_cnt1[GRPS], g_cnt2[GRPS];
__device__ volatile unsigned g_flag1[GRPS], g_flag2[GRPS];

__device__ __forceinline__ float ex2f(float x) {
    float r; asm("ex2.approx.f32 %0, %1;" : "=f"(r) : "f"(x)); return r;
}

// group barrier: waits for GBLKN blocks of this image group
__device__ __forceinline__ void grpbar(unsigned* cnt, volatile unsigned* flag) {
    __syncthreads();
    if (threadIdx.x == 0) {
        __threadfence();
        if (atomicAdd(cnt, 1u) == GBLKN - 1) *flag = 1u;
        else while (*flag == 0u) __nanosleep(32);
        __threadfence();
    }
    __syncthreads();
}

__global__ void __launch_bounds__(NTHR, 4)
k_fused(const float* __restrict__ s0, const float* __restrict__ s1,
        const int* __restrict__ tgt, float* __restrict__ out) {
    __shared__ float sA[NTHR];
    __shared__ float sB[NTHR];

    const int tid   = threadIdx.x;
    const int lane  = tid & 31;
    const int gimg  = blockIdx.x / GBLKN;        // image this group owns
    const int gblk  = blockIdx.x % GBLKN;        // block index within group
    const int ltid  = gblk * NTHR + tid;         // thread id within group
    const int lwarp = ltid >> 5;                 // warp id within group

    // ---------- Phase 1: pack THIS image's target bits ---------------------
    // 8 independent 128B loads per warp-iter; image = 16384 warp-iters.
    {
        const int* tg = tgt + (size_t)gimg * HW;
        unsigned* tb  = g_tbits + gimg * WPI;
        for (int w = lwarp; w < HW / 256; w += GWARPS) {
            int base = w * 256;
            int t0 = __ldcs(&tg[base + lane]);
            int t1 = __ldcs(&tg[base + 32 + lane]);
            int t2 = __ldcs(&tg[base + 64 + lane]);
            int t3 = __ldcs(&tg[base + 96 + lane]);
            int t4 = __ldcs(&tg[base + 128 + lane]);
            int t5 = __ldcs(&tg[base + 160 + lane]);
            int t6 = __ldcs(&tg[base + 192 + lane]);
            int t7 = __ldcs(&tg[base + 224 + lane]);
            unsigned b0 = __ballot_sync(0xffffffffu, t0 != 0);
            unsigned b1 = __ballot_sync(0xffffffffu, t1 != 0);
            unsigned b2 = __ballot_sync(0xffffffffu, t2 != 0);
            unsigned b3 = __ballot_sync(0xffffffffu, t3 != 0);
            unsigned b4 = __ballot_sync(0xffffffffu, t4 != 0);
            unsigned b5 = __ballot_sync(0xffffffffu, t5 != 0);
            unsigned b6 = __ballot_sync(0xffffffffu, t6 != 0);
            unsigned b7 = __ballot_sync(0xffffffffu, t7 != 0);
            if (lane == 0) {
                *(uint4*)&tb[w * 8]     = make_uint4(b0, b1, b2, b3);
                *(uint4*)&tb[w * 8 + 4] = make_uint4(b4, b5, b6, b7);
            }
        }
    }

    grpbar(&g_cnt1[gimg], &g_flag1[gimg]);

    // ---------- Phase 2: edge words for THIS image -> g_te -----------------
    unsigned ecnt = 0;
    {
        const unsigned* rb = g_tbits + gimg * WPI;
        uint2* te = g_te + gimg * WPI;
        for (int idx = ltid; idx < WPI; idx += GTHREADS) {
            int j = idx & (WORDS - 1);
            int y = idx >> 5;

            unsigned orL = 0, orM = 0, orR = 0;
            unsigned anL = ~0u, anM = ~0u, anR = ~0u;
            #pragma unroll
            for (int d = -5; d <= 5; ++d) {
                int r = y + d;
                unsigned wl = 0, wm = 0, wr = 0;
                if ((unsigned)r < HH) {
                    const unsigned* p = rb + r * WORDS;
                    wm = p[j];
                    wl = (j > 0)  ? p[j - 1] : 0u;
                    wr = (j < 31) ? p[j + 1] : 0u;
                }
                orL |= wl; orM |= wm; orR |= wr;
                anL &= wl; anM &= wm; anR &= wr;
            }
            unsigned nL = ~anL, nM = ~anM, nR = ~anR;
            unsigned any1 = orM, any0 = nM;
            #pragma unroll
            for (int s = 1; s <= 5; s++) {
                any1 |= __funnelshift_r(orM, orR, s);
                any1 |= __funnelshift_l(orL, orM, s);
                any0 |= __funnelshift_r(nM, nR, s);
                any0 |= __funnelshift_l(nL, nM, s);
            }
            unsigned T = rb[idx];
            unsigned e = (T & any0) | (~T & any1);
            te[idx] = make_uint2(T, e);
            ecnt += __popc(e);
        }
    }

    // ---------- Phase 3 setup ----------------------------------------------
    const float LOG2E = 1.4426950408889634f;
    const int rsub = tid >> 7;               // row within pair (0/1)
    const int c8   = (tid & 127) * 8;        // 8-px column
    const int wj8  = c8 >> 5;
    const int sh8  = c8 & 31;

    float accA = 0.f, accB = 0.f;

    // ---------- First pair (static = gblk): loads span barrier 2 -----------
    {
        unsigned row = (unsigned)gblk * 2u + rsub;       // gblk < 512 always
        unsigned widx = gimg * WPI + row * WORDS + wj8;
        unsigned pixbase = (unsigned)gimg * 2u * HW + row * WW + c8;
        const float* p00 = s0 + pixbase;
        const float* p10 = s1 + pixbase;

        float4 a0  = __ldcs((const float4*)(p00));
        float4 a0b = __ldcs((const float4*)(p00 + 4));
        float4 a1  = __ldcs((const float4*)(p00 + HW));
        float4 a1b = __ldcs((const float4*)(p00 + HW + 4));
        float4 c0  = __ldcs((const float4*)(p10));
        float4 c0b = __ldcs((const float4*)(p10 + 4));
        float4 c1  = __ldcs((const float4*)(p10 + HW));
        float4 c1b = __ldcs((const float4*)(p10 + HW + 4));

        grpbar(&g_cnt2[gimg], &g_flag2[gimg]);   // t/e words become valid

        uint2 te = g_te[widx];
        unsigned tw = te.x >> sh8;
        unsigned ew = te.y >> sh8;
        unsigned ntw = ~tw;

        float x0[8] = {a0.x, a0.y, a0.z, a0.w, a0b.x, a0b.y, a0b.z, a0b.w};
        float x1[8] = {a1.x, a1.y, a1.z, a1.w, a1b.x, a1b.y, a1b.z, a1b.w};
        float y0[8] = {c0.x, c0.y, c0.z, c0.w, c0b.x, c0b.y, c0b.z, c0b.w};
        float y1[8] = {c1.x, c1.y, c1.z, c1.w, c1b.x, c1b.y, c1b.z, c1b.w};

        #pragma unroll
        for (int k = 0; k < 8; k++) {
            unsigned sflip = (ntw << (31 - k)) & 0x80000000u;
            int      emask = ((int)(ew << (31 - k))) >> 31;
            float d2 = (x1[k] - x0[k]) * LOG2E;
            float u  = __int_as_float(__float_as_int(d2) ^ sflip);
            float z  = ex2f(-fabsf(u));
            float sp = fmaxf(-u, 0.f) + __log2f(1.f + z);
            float e2 = (y1[k] - y0[k]) * LOG2E;
            float v  = __int_as_float(__float_as_int(e2) ^ sflip);
            float z2 = ex2f(-fabsf(v));
            float sq = fmaxf(-v, 0.f) + __log2f(1.f + z2);
            accA += sp + 0.5f * sq;
            float Bt = (0.5f * sp + u) + 0.5f * (0.5f * sq + v);
            accB += __int_as_float(__float_as_int(Bt) & emask);
        }
    }

    // ---------- Phase 3: stream THIS image's scores (static stride) --------
    for (int it = gblk + GBLKN; it < PAIRS_IMG; it += GBLKN) {
        unsigned row = (unsigned)it * 2u + rsub;
        unsigned widx = gimg * WPI + row * WORDS + wj8;
        unsigned pixbase = (unsigned)gimg * 2u * HW + row * WW + c8;
        const float* p00 = s0 + pixbase;
        const float* p10 = s1 + pixbase;

        float4 a0  = __ldcs((const float4*)(p00));
        float4 a0b = __ldcs((const float4*)(p00 + 4));
        float4 a1  = __ldcs((const float4*)(p00 + HW));
        float4 a1b = __ldcs((const float4*)(p00 + HW + 4));
        float4 c0  = __ldcs((const float4*)(p10));
        float4 c0b = __ldcs((const float4*)(p10 + 4));
        float4 c1  = __ldcs((const float4*)(p10 + HW));
        float4 c1b = __ldcs((const float4*)(p10 + HW + 4));

        uint2 te = g_te[widx];
        unsigned tw = te.x >> sh8;
        unsigned ew = te.y >> sh8;
        unsigned ntw = ~tw;

        float x0[8] = {a0.x, a0.y, a0.z, a0.w, a0b.x, a0b.y, a0b.z, a0b.w};
        float x1[8] = {a1.x, a1.y, a1.z, a1.w, a1b.x, a1b.y, a1b.z, a1b.w};
        float y0[8] = {c0.x, c0.y, c0.z, c0.w, c0b.x, c0b.y, c0b.z, c0b.w};
        float y1[8] = {c1.x, c1.y, c1.z, c1.w, c1b.x, c1b.y, c1b.z, c1b.w};

        #pragma unroll
        for (int k = 0; k < 8; k++) {
            unsigned sflip = (ntw << (31 - k)) & 0x80000000u;
            int      emask = ((int)(ew << (31 - k))) >> 31;

            float d2 = (x1[k] - x0[k]) * LOG2E;
            float u  = __int_as_float(__float_as_int(d2) ^ sflip);
            float z  = ex2f(-fabsf(u));
            float sp = fmaxf(-u, 0.f) + __log2f(1.f + z);

            float e2 = (y1[k] - y0[k]) * LOG2E;
            float v  = __int_as_float(__float_as_int(e2) ^ sflip);
            float z2 = ex2f(-fabsf(v));
            float sq = fmaxf(-v, 0.f) + __log2f(1.f + z2);

            accA += sp + 0.5f * sq;
            float Bt = (0.5f * sp + u) + 0.5f * (0.5f * sq + v);
            accB += __int_as_float(__float_as_int(Bt) & emask);
        }
    }

    // ---------- Block reduction + global accumulation ----------------------
    ecnt = __reduce_add_sync(0xffffffffu, ecnt);

    sA[tid] = accA;
    sB[tid] = accB;
    __syncthreads();
    #pragma unroll
    for (int s = NTHR / 2; s > 0; s >>= 1) {
        if (tid < s) { sA[tid] += sA[tid + s]; sB[tid] += sB[tid + s]; }
        __syncthreads();
    }

    if (lane == 0 && ecnt)
        atomicAdd(&g_ecount, (unsigned long long)ecnt);

    if (tid == 0) {
        atomicAdd(&g_A, (double)sA[0]);
        atomicAdd(&g_B, (double)sB[0]);
        __threadfence();
        unsigned done = atomicAdd(&g_done, 1u);
        if (done == NBLK - 1) {
            const double LN2 = 0.6931471805599453;
            double N = (double)NPIX;
            double a = (double)g_ecount / N;
            if (a > 0.2) a = 0.2;
            out[0] = (float)((g_A + a * g_B) * LN2 / N);
            // reset ALL state for the next graph replay (all blocks are done,
            // hence past every group barrier)
            g_A = 0.0; g_B = 0.0; g_ecount = 0ull;
            #pragma unroll
            for (int i = 0; i < GRPS; i++) {
                g_cnt1[i] = 0u; g_flag1[i] = 0u;
                g_cnt2[i] = 0u; g_flag2[i] = 0u;
            }
            __threadfence();
            g_done = 0u;
        }
    }
}

// ---------------------------------------------------------------------------
extern "C" void kernel_launch(void* const* d_in, const int* in_sizes, int n_in,
                              void* d_out, int out_size) {
    int ti = 0;
    for (int i = 1; i < n_in; i++)
        if (in_sizes[i] < in_sizes[ti]) ti = i;
    const float* s0 = nullptr;
    const float* s1 = nullptr;
    for (int i = 0; i < n_in; i++) {
        if (i == ti) continue;
        if (!s0) s0 = (const float*)d_in[i];
        else     s1 = (const float*)d_in[i];
    }
    const int* tgt = (const int*)d_in[ti];

    k_fused<<<NBLK, NTHR>>>(s0, s1, tgt, (float*)d_out);
}